// round 14
// baseline (speedup 1.0000x reference)
#include <cuda_runtime.h>
#include <cuda_fp16.h>
#include <math.h>
#include <stdint.h>

// ---------------------------------------------------------------------------
// Problem constants
// ---------------------------------------------------------------------------
#define BB    2
#define SS    2048
#define DM    1024
#define HH    16
#define DHD   64
#define MTOK  (BB*SS)          // 4096 token rows
#define DFF   4096
#define NEGBIG (-1000000000.0f)

// ---------------------------------------------------------------------------
// Scratch (static device globals; no allocations allowed)
// ---------------------------------------------------------------------------
__device__ float  g_X  [MTOK*DM];             // LN out, exact (residuals)
__device__ __half g_XR [MTOK*DM];             // LN out, fp16 (GEMM A)
__device__ __half g_ER [MTOK*DM];             // input_embedding, fp16
__device__ __half g_QKV[(size_t)MTOK*3*DM];   // packed Q|K|V (self-attn)
__device__ __half g_KV [(size_t)MTOK*2*DM];   // packed K|V (cross-attn)
__device__ __half g_Q  [MTOK*DM];             // Q2
__device__ __half g_ATT[MTOK*DM];             // attention out (fp16)
__device__ float  g_H  [MTOK*DM];             // residual stream, exact
__device__ __half g_HID[(size_t)MTOK*DFF];    // MLP hidden (fp16)
__device__ __half g_WTh[16*1024*1024];        // fp16 weights, K-major [N][K]
__device__ float  g_BI [3*DM + 2*DM];         // concat biases qkv1, kv2

// ---------------------------------------------------------------------------
// Helpers
// ---------------------------------------------------------------------------
__device__ __forceinline__ uint32_t h2_u32(__half2 h) {
    return *(uint32_t*)&h;
}

__device__ __forceinline__ void mma_f16(float* d, const uint32_t* a,
                                        const uint32_t* b) {
    asm volatile(
        "mma.sync.aligned.m16n8k16.row.col.f32.f16.f16.f32 "
        "{%0,%1,%2,%3}, {%4,%5,%6,%7}, {%8,%9}, {%0,%1,%2,%3};"
        : "+f"(d[0]), "+f"(d[1]), "+f"(d[2]), "+f"(d[3])
        : "r"(a[0]), "r"(a[1]), "r"(a[2]), "r"(a[3]), "r"(b[0]), "r"(b[1]));
}

__device__ __forceinline__ uint32_t smem_u32(const void* p) {
    uint32_t a;
    asm("{ .reg .u64 t; cvta.to.shared.u64 t, %1; cvt.u32.u64 %0, t; }"
        : "=r"(a) : "l"(p));
    return a;
}
__device__ __forceinline__ void cp16(uint32_t dst, const void* src) {
    asm volatile("cp.async.cg.shared.global [%0], [%1], 16;"
                 :: "r"(dst), "l"(src));
}
#define CP_COMMIT() asm volatile("cp.async.commit_group;" ::: "memory")
#define CP_WAIT(n)  asm volatile("cp.async.wait_group %0;" :: "n"(n) : "memory")

// ---------------------------------------------------------------------------
// Batched weight transpose + fp16 convert: 8x [DM][DM] fp32 -> half [DM][DM]^T
// ---------------------------------------------------------------------------
struct TransBatch {
    const float* src[8];
    __half* dst[8];
};

__global__ void trans_h8(TransBatch tb) {
    __shared__ float tile[32][33];
    const float* in = tb.src[blockIdx.z];
    __half* out = tb.dst[blockIdx.z];
    int cx = blockIdx.x * 32, ry = blockIdx.y * 32;
    int tx = threadIdx.x, ty = threadIdx.y;
#pragma unroll
    for (int i = 0; i < 32; i += 8)
        tile[ty + i][tx] = in[(size_t)(ry + ty + i) * DM + cx + tx];
    __syncthreads();
#pragma unroll
    for (int i = 0; i < 32; i += 8)
        out[(size_t)(cx + ty + i) * DM + ry + tx] =
            __float2half_rn(tile[tx][ty + i]);
}

// generic single transpose (for MLP weights)
__global__ void trans_h(const float* __restrict__ in, __half* __restrict__ out,
                        int R, int C) {
    __shared__ float tile[32][33];
    int cx = blockIdx.x * 32, ry = blockIdx.y * 32;
    int tx = threadIdx.x, ty = threadIdx.y;
#pragma unroll
    for (int i = 0; i < 32; i += 8)
        tile[ty + i][tx] = in[(size_t)(ry + ty + i) * C + cx + tx];
    __syncthreads();
#pragma unroll
    for (int i = 0; i < 32; i += 8)
        out[(size_t)(cx + ty + i) * R + ry + tx] =
            __float2half_rn(tile[tx][ty + i]);
}

// elementwise fp32 -> fp16
__global__ void round_h(const float* __restrict__ in, __half* __restrict__ out,
                        int n4) {
    int i = blockIdx.x * 256 + threadIdx.x;
    if (i < n4) {
        float4 v = ((const float4*)in)[i];
        uint2 o;
        o.x = h2_u32(__floats2half2_rn(v.x, v.y));
        o.y = h2_u32(__floats2half2_rn(v.z, v.w));
        ((uint2*)out)[i] = o;
    }
}

// concat biases: out[0:3D) = q1_b|k1_b|v1_b ; out[3D:5D) = k2_b|v2_b
__global__ void bias_concat(const float* q1b, const float* k1b, const float* v1b,
                            const float* k2b, const float* v2b, float* out) {
    int i = blockIdx.x * 256 + threadIdx.x;
    if (i < DM)            out[i] = q1b[i];
    else if (i < 2 * DM)   out[i] = k1b[i - DM];
    else if (i < 3 * DM)   out[i] = v1b[i - 2 * DM];
    else if (i < 4 * DM)   out[i] = k2b[i - 3 * DM];
    else if (i < 5 * DM)   out[i] = v2b[i - 4 * DM];
}

// ---------------------------------------------------------------------------
// Block reduction for (sum, sumsq), blockDim.x == 256
// ---------------------------------------------------------------------------
__device__ __forceinline__ void block_reduce_2(float& s, float& q) {
    __shared__ float sh_s[8], sh_q[8];
    int lane = threadIdx.x & 31, w = threadIdx.x >> 5;
#pragma unroll
    for (int o = 16; o > 0; o >>= 1) {
        s += __shfl_down_sync(0xffffffffu, s, o);
        q += __shfl_down_sync(0xffffffffu, q, o);
    }
    if (lane == 0) { sh_s[w] = s; sh_q[w] = q; }
    __syncthreads();
    if (w == 0) {
        s = (lane < 8) ? sh_s[lane] : 0.f;
        q = (lane < 8) ? sh_q[lane] : 0.f;
#pragma unroll
        for (int o = 4; o > 0; o >>= 1) {
            s += __shfl_down_sync(0xffffffffu, s, o);
            q += __shfl_down_sync(0xffffffffu, q, o);
        }
        if (lane == 0) { sh_s[0] = s; sh_q[0] = q; }
    }
    __syncthreads();
    s = sh_s[0]; q = sh_q[0];
}

// ---------------------------------------------------------------------------
// Embedding gather + positional + LayerNorm; exact fp32 + fp16 outputs
// ---------------------------------------------------------------------------
__global__ void embed_ln_kernel(const int* __restrict__ tgt_ids,
                                const float* __restrict__ tok_emb,
                                const float* __restrict__ pos_emb,
                                const float* __restrict__ gam,
                                const float* __restrict__ bet,
                                float* __restrict__ out,
                                __half* __restrict__ out_r) {
    int row = blockIdx.x;
    int s   = row & (SS - 1);
    int tok = tgt_ids[row];
    const float* te = tok_emb + (size_t)tok * DM;
    const float* pe = pos_emb + (size_t)s   * DM;
    float v[4]; float sum = 0.f, sq = 0.f;
#pragma unroll
    for (int i = 0; i < 4; i++) {
        int c = threadIdx.x + i * 256;
        float x = te[c] + pe[c];
        v[i] = x; sum += x; sq += x * x;
    }
    block_reduce_2(sum, sq);
    float mu  = sum * (1.f / DM);
    float var = sq * (1.f / DM) - mu * mu;
    float rs  = rsqrtf(var + 1e-5f);
    float*  o   = out   + (size_t)row * DM;
    __half* orr = out_r + (size_t)row * DM;
#pragma unroll
    for (int i = 0; i < 4; i++) {
        int c = threadIdx.x + i * 256;
        float y = (v[i] - mu) * rs * gam[c] + bet[c];
        o[c] = y;
        orr[c] = __float2half_rn(y);
    }
}

// ---------------------------------------------------------------------------
// LayerNorm; exact fp32 + fp16 outputs
// ---------------------------------------------------------------------------
__global__ void ln_kernel(const float* __restrict__ in,
                          const float* __restrict__ gam,
                          const float* __restrict__ bet,
                          float* __restrict__ out,
                          __half* __restrict__ out_r) {
    int row = blockIdx.x;
    const float* ip = in + (size_t)row * DM;
    float v[4]; float sum = 0.f, sq = 0.f;
#pragma unroll
    for (int i = 0; i < 4; i++) {
        int c = threadIdx.x + i * 256;
        float x = ip[c];
        v[i] = x; sum += x; sq += x * x;
    }
    block_reduce_2(sum, sq);
    float mu  = sum * (1.f / DM);
    float var = sq * (1.f / DM) - mu * mu;
    float rs  = rsqrtf(var + 1e-5f);
    float*  o   = out   + (size_t)row * DM;
    __half* orr = out_r + (size_t)row * DM;
#pragma unroll
    for (int i = 0; i < 4; i++) {
        int c = threadIdx.x + i * 256;
        float y = (v[i] - mu) * rs * gam[c] + bet[c];
        o[c] = y;
        orr[c] = __float2half_rn(y);
    }
}

// ---------------------------------------------------------------------------
// FP16 mma.sync GEMM: C[M,N] = A[M,K] @ W^T (W [N][K] half) + bias (+res)
// (gelu opt). 128(M)x256(N) CTA tile, 256 threads (8 warps 2m x 4n, 64x64),
// BK=64, 3-stage cp.async pipeline. C half (out_half=1) or float.
// ---------------------------------------------------------------------------
#define BKH    64
#define PADH   72                              // halfs per smem row
#define TILE_A_H (128 * PADH)                  // A halfs per stage
#define TILE_B_H (256 * PADH)                  // B halfs per stage
#define STAGE_H  (TILE_A_H + TILE_B_H)
#define GEMM_SMEM_BYTES (3 * STAGE_H * 2)      // 165888 B

__global__ __launch_bounds__(256) void gemm_h(
    const __half* __restrict__ A, const __half* __restrict__ W,
    const float* __restrict__ bias, const float* __restrict__ res,
    void* __restrict__ Cout, int M, int N, int K, int gelu, int out_half) {
    extern __shared__ __half smh[];
    uint32_t sbase = smem_u32(smh);

    int tid  = threadIdx.x;
    int wid  = tid >> 5, lane = tid & 31;
    int gid  = lane >> 2, tig = lane & 3;
    int m_off = (wid >> 2) * 64;
    int n_off = (wid & 3) * 64;
    int bm = blockIdx.y * 128, bn = blockIdx.x * 256;

    float acc[4][8][4];
#pragma unroll
    for (int i = 0; i < 4; i++)
#pragma unroll
        for (int j = 0; j < 8; j++)
#pragma unroll
            for (int k = 0; k < 4; k++) acc[i][j][k] = 0.f;

    const int T = K / BKH;

    auto issue = [&](int s, int kt) {
        uint32_t aU = sbase + (uint32_t)(s * STAGE_H) * 2;
        uint32_t bU = aU + (uint32_t)TILE_A_H * 2;
        int k0 = kt * BKH;
#pragma unroll
        for (int i = 0; i < 4; i++) {
            int idx = tid + i * 256;
            int r = idx >> 3, c8 = (idx & 7) * 8;
            cp16(aU + (uint32_t)(r * PADH + c8) * 2,
                 A + (size_t)(bm + r) * K + k0 + c8);
        }
#pragma unroll
        for (int i = 0; i < 8; i++) {
            int idx = tid + i * 256;
            int r = idx >> 3, c8 = (idx & 7) * 8;
            cp16(bU + (uint32_t)(r * PADH + c8) * 2,
                 W + (size_t)(bn + r) * K + k0 + c8);
        }
        CP_COMMIT();
    };

    issue(0, 0);
    issue(1, 1);

    for (int t = 0; t < T; t++) {
        int cur = t % 3;
        CP_WAIT(1);
        __syncthreads();
        if (t + 2 < T) issue((t + 2) % 3, t + 2);

        const __half* Ah = smh + cur * STAGE_H;
        const __half* Bh = Ah + TILE_A_H;
#pragma unroll
        for (int ks = 0; ks < 4; ks++) {
            int k = ks * 16;
            uint32_t a[4][4], b[8][2];
#pragma unroll
            for (int mf = 0; mf < 4; mf++) {
                const __half* p = Ah + (m_off + mf * 16 + gid) * PADH + k + 2 * tig;
                a[mf][0] = *(const uint32_t*)(p);
                a[mf][1] = *(const uint32_t*)(p + 8 * PADH);
                a[mf][2] = *(const uint32_t*)(p + 8);
                a[mf][3] = *(const uint32_t*)(p + 8 * PADH + 8);
            }
#pragma unroll
            for (int nf = 0; nf < 8; nf++) {
                const __half* p = Bh + (n_off + nf * 8 + gid) * PADH + k + 2 * tig;
                b[nf][0] = *(const uint32_t*)(p);
                b[nf][1] = *(const uint32_t*)(p + 8);
            }
#pragma unroll
            for (int mf = 0; mf < 4; mf++)
#pragma unroll
                for (int nf = 0; nf < 8; nf++)
                    mma_f16(acc[mf][nf], a[mf], b[nf]);
        }
    }

#pragma unroll
    for (int mf = 0; mf < 4; mf++) {
        int row0 = bm + m_off + mf * 16 + gid;
        int row1 = row0 + 8;
#pragma unroll
        for (int nf = 0; nf < 8; nf++) {
            int col = bn + n_off + nf * 8 + 2 * tig;
            float b0 = bias[col], b1 = bias[col + 1];
            float v0 = acc[mf][nf][0] + b0;
            float v1 = acc[mf][nf][1] + b1;
            float v2 = acc[mf][nf][2] + b0;
            float v3 = acc[mf][nf][3] + b1;
            if (res) {
                v0 += res[(size_t)row0 * N + col];
                v1 += res[(size_t)row0 * N + col + 1];
                v2 += res[(size_t)row1 * N + col];
                v3 += res[(size_t)row1 * N + col + 1];
            }
            if (gelu) {
                v0 = 0.5f * v0 * (1.0f + erff(v0 * 0.70710678118654752f));
                v1 = 0.5f * v1 * (1.0f + erff(v1 * 0.70710678118654752f));
                v2 = 0.5f * v2 * (1.0f + erff(v2 * 0.70710678118654752f));
                v3 = 0.5f * v3 * (1.0f + erff(v3 * 0.70710678118654752f));
            }
            if (out_half) {
                __half* C = (__half*)Cout;
                *(__half2*)(C + (size_t)row0 * N + col) = __floats2half2_rn(v0, v1);
                *(__half2*)(C + (size_t)row1 * N + col) = __floats2half2_rn(v2, v3);
            } else {
                float* C = (float*)Cout;
                *(float2*)(C + (size_t)row0 * N + col) = make_float2(v0, v1);
                *(float2*)(C + (size_t)row1 * N + col) = make_float2(v2, v3);
            }
        }
    }
}

// ---------------------------------------------------------------------------
// FP16 tensor-core flash attention with register-prefetch pipeline.
// Q/K/V half (packed strides), O half. 128 threads, 64 q-rows/block.
// ---------------------------------------------------------------------------
#define AP 72
#define ATTN_SMEM_BYTES (3 * 64 * AP * 2 + 64 * 4)

__global__ __launch_bounds__(128) void attn_h(
    const __half* __restrict__ Q, const __half* __restrict__ Kb,
    const __half* __restrict__ Vb, const int* __restrict__ ids,
    __half* __restrict__ O, int causal, int stq, int stkv) {
    extern __shared__ __half smh[];
    __half* Ks = smh;                  // [64][AP]  keys x dh
    __half* Vt = smh + 64 * AP;        // [64][AP]  dh x keys
    __half* Ps = smh + 2 * 64 * AP;    // [64][AP]  q x keys
    float*  pm = (float*)(smh + 3 * 64 * AP);

    int b   = blockIdx.y >> 4;
    int h   = blockIdx.y & 15;
    int q0  = blockIdx.x * 64;
    int tid = threadIdx.x;
    int wid = tid >> 5, lane = tid & 31;
    int gid = lane >> 2, tig = lane & 3;
    int lrow = wid * 16 + gid;
    int grow = q0 + lrow;

    // Q fragments (A operand), 4 k-steps of 16 dh
    uint32_t qf[4][4];
    const __half* qb0 = Q + ((size_t)(b * SS + grow)) * stq + h * DHD;
    const __half* qb8 = qb0 + (size_t)8 * stq;
#pragma unroll
    for (int ks = 0; ks < 4; ks++) {
        int k = ks * 16 + 2 * tig;
        qf[ks][0] = *(const uint32_t*)(qb0 + k);
        qf[ks][1] = *(const uint32_t*)(qb8 + k);
        qf[ks][2] = *(const uint32_t*)(qb0 + k + 8);
        qf[ks][3] = *(const uint32_t*)(qb8 + k + 8);
    }

    float of[8][4];
#pragma unroll
    for (int i = 0; i < 8; i++)
#pragma unroll
        for (int j = 0; j < 4; j++) of[i][j] = 0.f;
    float m0 = -1e30f, m1 = -1e30f, l0 = 0.f, l1 = 0.f;

    int ntiles = causal ? (blockIdx.x + 1) : (SS / 64);

    // register prefetch state
    uint4 kvr[4], vvr[4];
    int idv = 0;
    auto loadtile = [&](int t) {
        int kbase = t * 64;
#pragma unroll
        for (int i = 0; i < 4; i++) {
            int e  = tid + i * 128;
            int r  = e >> 3, c8 = (e & 7) * 8;
            size_t goff = ((size_t)(b * SS + kbase + r)) * stkv + h * DHD + c8;
            kvr[i] = *(const uint4*)(Kb + goff);
            vvr[i] = *(const uint4*)(Vb + goff);
        }
        if (tid < 64) idv = ids[b * SS + kbase + tid];
    };

    loadtile(0);
    for (int t = 0; t < ntiles; t++) {
        int kbase = t * 64;
        // store phase (from registers)
#pragma unroll
        for (int i = 0; i < 4; i++) {
            int e  = tid + i * 128;
            int r  = e >> 3, c8 = (e & 7) * 8;
            *(uint4*)(Ks + r * AP + c8) = kvr[i];
            const __half* vh = (const __half*)&vvr[i];
#pragma unroll
            for (int j = 0; j < 8; j++)
                Vt[(c8 + j) * AP + r] = vh[j];
        }
        if (tid < 64)
            pm[tid] = (idv == 0) ? NEGBIG : 0.f;
        __syncthreads();
        if (t + 1 < ntiles) loadtile(t + 1);

        // S = Q @ K^T
        float sf[8][4];
#pragma unroll
        for (int nf = 0; nf < 8; nf++) {
            sf[nf][0] = 0.f; sf[nf][1] = 0.f; sf[nf][2] = 0.f; sf[nf][3] = 0.f;
#pragma unroll
            for (int ks = 0; ks < 4; ks++) {
                uint32_t bf[2];
                const __half* p = Ks + (nf * 8 + gid) * AP + ks * 16 + 2 * tig;
                bf[0] = *(const uint32_t*)(p);
                bf[1] = *(const uint32_t*)(p + 8);
                mma_f16(sf[nf], qf[ks], bf);
            }
        }

        float tmax0 = -1e30f, tmax1 = -1e30f;
#pragma unroll
        for (int nf = 0; nf < 8; nf++) {
            int lc0 = nf * 8 + 2 * tig, lc1 = lc0 + 1;
            float s0 = sf[nf][0] * 0.125f + pm[lc0];
            float s1 = sf[nf][1] * 0.125f + pm[lc1];
            float s2 = sf[nf][2] * 0.125f + pm[lc0];
            float s3 = sf[nf][3] * 0.125f + pm[lc1];
            if (causal) {
                int g0 = kbase + lc0, g1 = kbase + lc1;
                if (g0 > grow)     s0 = -1e30f;
                if (g1 > grow)     s1 = -1e30f;
                if (g0 > grow + 8) s2 = -1e30f;
                if (g1 > grow + 8) s3 = -1e30f;
            }
            sf[nf][0] = s0; sf[nf][1] = s1; sf[nf][2] = s2; sf[nf][3] = s3;
            tmax0 = fmaxf(tmax0, fmaxf(s0, s1));
            tmax1 = fmaxf(tmax1, fmaxf(s2, s3));
        }
        tmax0 = fmaxf(tmax0, __shfl_xor_sync(0xffffffffu, tmax0, 1));
        tmax0 = fmaxf(tmax0, __shfl_xor_sync(0xffffffffu, tmax0, 2));
        tmax1 = fmaxf(tmax1, __shfl_xor_sync(0xffffffffu, tmax1, 1));
        tmax1 = fmaxf(tmax1, __shfl_xor_sync(0xffffffffu, tmax1, 2));

        float nm0 = fmaxf(m0, tmax0), nm1 = fmaxf(m1, tmax1);
        float sc0 = __expf(m0 - nm0), sc1 = __expf(m1 - nm1);
        m0 = nm0; m1 = nm1;

        float ts0 = 0.f, ts1 = 0.f;
        __half* pr0 = Ps + lrow * AP;
        __half* pr1 = Ps + (lrow + 8) * AP;
#pragma unroll
        for (int nf = 0; nf < 8; nf++) {
            int lc0 = nf * 8 + 2 * tig;
            float p0 = __expf(sf[nf][0] - nm0);
            float p1 = __expf(sf[nf][1] - nm0);
            float p2 = __expf(sf[nf][2] - nm1);
            float p3 = __expf(sf[nf][3] - nm1);
            ts0 += p0 + p1; ts1 += p2 + p3;
            *(__half2*)(pr0 + lc0) = __floats2half2_rn(p0, p1);
            *(__half2*)(pr1 + lc0) = __floats2half2_rn(p2, p3);
            of[nf][0] *= sc0; of[nf][1] *= sc0;
            of[nf][2] *= sc1; of[nf][3] *= sc1;
        }
        ts0 += __shfl_xor_sync(0xffffffffu, ts0, 1);
        ts0 += __shfl_xor_sync(0xffffffffu, ts0, 2);
        ts1 += __shfl_xor_sync(0xffffffffu, ts1, 1);
        ts1 += __shfl_xor_sync(0xffffffffu, ts1, 2);
        l0 = l0 * sc0 + ts0;
        l1 = l1 * sc1 + ts1;
        __syncwarp();

        // O += P @ V
#pragma unroll
        for (int ks = 0; ks < 4; ks++) {
            int kk = ks * 16 + 2 * tig;
            uint32_t af[4];
            af[0] = *(const uint32_t*)(pr0 + kk);
            af[1] = *(const uint32_t*)(pr1 + kk);
            af[2] = *(const uint32_t*)(pr0 + kk + 8);
            af[3] = *(const uint32_t*)(pr1 + kk + 8);
#pragma unroll
            for (int nf = 0; nf < 8; nf++) {
                uint32_t bf[2];
                const __half* p = Vt + (nf * 8 + gid) * AP + ks * 16 + 2 * tig;
                bf[0] = *(const uint32_t*)(p);
                bf[1] = *(const uint32_t*)(p + 8);
                mma_f16(of[nf], af, bf);
            }
        }
        __syncthreads();
    }

    float inv0 = 1.f / l0, inv1 = 1.f / l1;
    __half* ob0 = O + ((size_t)(b * SS + grow)) * DM + h * DHD;
    __half* ob8 = ob0 + (size_t)8 * DM;
#pragma unroll
    for (int nf = 0; nf < 8; nf++) {
        int col = nf * 8 + 2 * tig;
        *(__half2*)(ob0 + col) = __floats2half2_rn(of[nf][0] * inv0, of[nf][1] * inv0);
        *(__half2*)(ob8 + col) = __floats2half2_rn(of[nf][2] * inv1, of[nf][3] * inv1);
    }
}

// ---------------------------------------------------------------------------
// Launch
// ---------------------------------------------------------------------------
extern "C" void kernel_launch(void* const* d_in, const int* in_sizes, int n_in,
                              void* d_out, int out_size) {
    const float* input_embedding = (const float*)d_in[0];
    const int*   input_ids       = (const int*)d_in[1];
    const int*   target_ids      = (const int*)d_in[2];
    const float* tok_emb = (const float*)d_in[3];
    const float* pos_emb = (const float*)d_in[4];
    const float* ln1_g = (const float*)d_in[5];
    const float* ln1_b = (const float*)d_in[6];
    const float* q1_w = (const float*)d_in[7];
    const float* q1_b = (const float*)d_in[8];
    const float* k1_w = (const float*)d_in[9];
    const float* k1_b = (const float*)d_in[10];
    const float* v1_w = (const float*)d_in[11];
    const float* v1_b = (const float*)d_in[12];
    const float* out1_w = (const float*)d_in[13];
    const float* out1_b = (const float*)d_in[14];
    const float* ln2_g = (const float*)d_in[15];
    const float* ln2_b = (const float*)d_in[16];
    const float* q2_w = (const float*)d_in[17];
    const float* q2_b = (const float*)d_in[18];
    const float* k2_w = (const float*)d_in[19];
    const float* k2_b = (const float*)d_in[20];
    const float* v2_w = (const float*)d_in[21];
    const float* v2_b = (const float*)d_in[22];
    const float* out2_w = (const float*)d_in[23];
    const float* out2_b = (const float*)d_in[24];
    const float* ln3_g = (const float*)d_in[25];
    const float* ln3_b = (const float*)d_in[26];
    const float* mlp_w1 = (const float*)d_in[27];
    const float* mlp_b1 = (const float*)d_in[28];
    const float* mlp_w2 = (const float*)d_in[29];
    const float* mlp_b2 = (const float*)d_in[30];
    float* out = (float*)d_out;

    static float  *X = nullptr, *H = nullptr, *BI = nullptr;
    static __half *XR = nullptr, *ER = nullptr, *QKV = nullptr, *KV = nullptr,
                  *Qh = nullptr, *ATT = nullptr, *HID = nullptr, *WTh = nullptr;
    static bool attr_done = false;
    if (!X) {
        cudaGetSymbolAddress((void**)&X,   g_X);
        cudaGetSymbolAddress((void**)&XR,  g_XR);
        cudaGetSymbolAddress((void**)&ER,  g_ER);
        cudaGetSymbolAddress((void**)&QKV, g_QKV);
        cudaGetSymbolAddress((void**)&KV,  g_KV);
        cudaGetSymbolAddress((void**)&Qh,  g_Q);
        cudaGetSymbolAddress((void**)&ATT, g_ATT);
        cudaGetSymbolAddress((void**)&H,   g_H);
        cudaGetSymbolAddress((void**)&HID, g_HID);
        cudaGetSymbolAddress((void**)&WTh, g_WTh);
        cudaGetSymbolAddress((void**)&BI,  g_BI);
    }
    if (!attr_done) {
        cudaFuncSetAttribute(gemm_h, cudaFuncAttributeMaxDynamicSharedMemorySize,
                             GEMM_SMEM_BYTES);
        cudaFuncSetAttribute(attn_h, cudaFuncAttributeMaxDynamicSharedMemorySize,
                             ATTN_SMEM_BYTES);
        attr_done = true;
    }

    const size_t MH = 1024 * 1024;
    __half* wr_qkv = WTh + 0 * MH;    // [3072][1024]
    __half* wr_kv2 = WTh + 3 * MH;    // [2048][1024]
    __half* wr_q2  = WTh + 5 * MH;    // [1024][1024]
    __half* wr_o1  = WTh + 6 * MH;
    __half* wr_o2  = WTh + 7 * MH;
    __half* wr_m1  = WTh + 8 * MH;    // [4096][1024]
    __half* wr_m2  = WTh + 12 * MH;   // [1024][4096]
    float* bqkv = BI;
    float* bkv2 = BI + 3 * DM;

    // batched DM x DM weight transposes (8 in one launch)
    TransBatch tbat;
    tbat.src[0] = q1_w;   tbat.dst[0] = wr_qkv;
    tbat.src[1] = k1_w;   tbat.dst[1] = wr_qkv + (size_t)DM * DM;
    tbat.src[2] = v1_w;   tbat.dst[2] = wr_qkv + (size_t)2 * DM * DM;
    tbat.src[3] = k2_w;   tbat.dst[3] = wr_kv2;
    tbat.src[4] = v2_w;   tbat.dst[4] = wr_kv2 + (size_t)DM * DM;
    tbat.src[5] = q2_w;   tbat.dst[5] = wr_q2;
    tbat.src[6] = out1_w; tbat.dst[6] = wr_o1;
    tbat.src[7] = out2_w; tbat.dst[7] = wr_o2;
    dim3 tb(32, 8);
    dim3 tg8(DM / 32, DM / 32, 8);
    trans_h8<<<tg8, tb>>>(tbat);
    dim3 tgm1(DFF / 32, DM / 32);            // mlp_w1 [1024][4096]
    trans_h<<<tgm1, tb>>>(mlp_w1, wr_m1, DM, DFF);
    dim3 tgm2(DM / 32, DFF / 32);            // mlp_w2 [4096][1024]
    trans_h<<<tgm2, tb>>>(mlp_w2, wr_m2, DFF, DM);
    round_h<<<(MTOK * DM / 4) / 256, 256>>>(input_embedding, ER, MTOK * DM / 4);
    bias_concat<<<20, 256>>>(q1_b, k1_b, v1_b, k2_b, v2_b, BI);

    dim3 gQKV(3 * DM / 256, MTOK / 128);   // (12, 32)
    dim3 gKV (2 * DM / 256, MTOK / 128);   // (8, 32)
    dim3 gProj(DM / 256, MTOK / 128);      // (4, 32)
    dim3 gMlp1(DFF / 256, MTOK / 128);     // (16, 32)
    dim3 gAttn(SS / 64, BB * HH);          // (32, 32)
    const int SB = GEMM_SMEM_BYTES;
    const int AB = ATTN_SMEM_BYTES;

    // 1. embedding + LN1 -> X (fp32), XR (fp16)
    embed_ln_kernel<<<MTOK, 256>>>(target_ids, tok_emb, pos_emb, ln1_g, ln1_b, X, XR);
    // 2. fused QKV projection -> QKV (fp16)
    gemm_h<<<gQKV, 256, SB>>>(XR, wr_qkv, bqkv, nullptr, QKV, MTOK, 3 * DM, DM, 0, 1);
    // 3. causal self-attention (packed QKV, stride 3*DM) -> ATT (fp16)
    attn_h<<<gAttn, 128, AB>>>(QKV, QKV + DM, QKV + 2 * DM, target_ids, ATT, 1,
                               3 * DM, 3 * DM);
    // 4. out projection + residual (X) -> H (fp32)
    gemm_h<<<gProj, 256, SB>>>(ATT, wr_o1, out1_b, X, H, MTOK, DM, DM, 0, 0);
    // 5. LN2 -> X, XR
    ln_kernel<<<MTOK, 256>>>(H, ln2_g, ln2_b, X, XR);
    // 6. cross-attn projections: Q2 (from XR), fused KV2 (from ER)
    gemm_h<<<gProj, 256, SB>>>(XR, wr_q2, q2_b, nullptr, Qh, MTOK, DM, DM, 0, 1);
    gemm_h<<<gKV, 256, SB>>>(ER, wr_kv2, bkv2, nullptr, KV, MTOK, 2 * DM, DM, 0, 1);
    // 7. cross-attention (Q stride DM, KV stride 2*DM) -> ATT (fp16)
    attn_h<<<gAttn, 128, AB>>>(Qh, KV, KV + DM, input_ids, ATT, 0, DM, 2 * DM);
    // 8. out projection + residual (X = LN2 out) -> H (fp32, "r")
    gemm_h<<<gProj, 256, SB>>>(ATT, wr_o2, out2_b, X, H, MTOK, DM, DM, 0, 0);
    // 9. LN3 -> X, XR
    ln_kernel<<<MTOK, 256>>>(H, ln3_g, ln3_b, X, XR);
    // 10. MLP up + GELU -> HID (fp16)
    gemm_h<<<gMlp1, 256, SB>>>(XR, wr_m1, mlp_b1, nullptr, HID, MTOK, DFF, DM, 1, 1);
    // 11. MLP down + bias + residual (H) -> out (fp32)
    gemm_h<<<gProj, 256, SB>>>(HID, wr_m2, mlp_b2, H, out, MTOK, DM, DFF, 0, 0);
}

// round 15
// speedup vs baseline: 1.0125x; 1.0125x over previous
#include <cuda_runtime.h>
#include <cuda_fp16.h>
#include <math.h>
#include <stdint.h>

// ---------------------------------------------------------------------------
// Problem constants
// ---------------------------------------------------------------------------
#define BB    2
#define SS    2048
#define DM    1024
#define HH    16
#define DHD   64
#define MTOK  (BB*SS)          // 4096 token rows
#define DFF   4096
#define NEGBIG (-1000000000.0f)

// ---------------------------------------------------------------------------
// Scratch (static device globals; no allocations allowed)
// ---------------------------------------------------------------------------
__device__ float  g_X  [MTOK*DM];             // LN out, exact (residuals)
__device__ __half g_XR [MTOK*DM];             // LN out, fp16 (GEMM A)
__device__ __half g_ER [MTOK*DM];             // input_embedding, fp16
__device__ __half g_QKV[(size_t)MTOK*3*DM];   // packed Q|K|V (self-attn)
__device__ __half g_KV [(size_t)MTOK*2*DM];   // packed K|V (cross-attn)
__device__ __half g_Q  [MTOK*DM];             // Q2
__device__ __half g_ATT[MTOK*DM];             // attention out (fp16)
__device__ float  g_H  [MTOK*DM];             // residual stream, exact
__device__ __half g_HID[(size_t)MTOK*DFF];    // MLP hidden (fp16)
__device__ __half g_WTh[16*1024*1024];        // fp16 weights, K-major [N][K]
__device__ float  g_BI [3*DM + 2*DM];         // concat biases qkv1, kv2

// ---------------------------------------------------------------------------
// Helpers
// ---------------------------------------------------------------------------
__device__ __forceinline__ uint32_t h2_u32(__half2 h) {
    return *(uint32_t*)&h;
}

__device__ __forceinline__ void mma_f16(float* d, const uint32_t* a,
                                        const uint32_t* b) {
    asm volatile(
        "mma.sync.aligned.m16n8k16.row.col.f32.f16.f16.f32 "
        "{%0,%1,%2,%3}, {%4,%5,%6,%7}, {%8,%9}, {%0,%1,%2,%3};"
        : "+f"(d[0]), "+f"(d[1]), "+f"(d[2]), "+f"(d[3])
        : "r"(a[0]), "r"(a[1]), "r"(a[2]), "r"(a[3]), "r"(b[0]), "r"(b[1]));
}

__device__ __forceinline__ uint32_t smem_u32(const void* p) {
    uint32_t a;
    asm("{ .reg .u64 t; cvta.to.shared.u64 t, %1; cvt.u32.u64 %0, t; }"
        : "=r"(a) : "l"(p));
    return a;
}
__device__ __forceinline__ void cp16(uint32_t dst, const void* src) {
    asm volatile("cp.async.cg.shared.global [%0], [%1], 16;"
                 :: "r"(dst), "l"(src));
}
#define CP_COMMIT() asm volatile("cp.async.commit_group;" ::: "memory")
#define CP_WAIT(n)  asm volatile("cp.async.wait_group %0;" :: "n"(n) : "memory")

// ---------------------------------------------------------------------------
// Batched weight transpose + fp16 convert: 8x [DM][DM] fp32 -> half [DM][DM]^T
// ---------------------------------------------------------------------------
struct TransBatch {
    const float* src[8];
    __half* dst[8];
};

__global__ void trans_h8(TransBatch tb) {
    __shared__ float tile[32][33];
    const float* in = tb.src[blockIdx.z];
    __half* out = tb.dst[blockIdx.z];
    int cx = blockIdx.x * 32, ry = blockIdx.y * 32;
    int tx = threadIdx.x, ty = threadIdx.y;
#pragma unroll
    for (int i = 0; i < 32; i += 8)
        tile[ty + i][tx] = in[(size_t)(ry + ty + i) * DM + cx + tx];
    __syncthreads();
#pragma unroll
    for (int i = 0; i < 32; i += 8)
        out[(size_t)(cx + ty + i) * DM + ry + tx] =
            __float2half_rn(tile[tx][ty + i]);
}

// generic single transpose (for MLP weights)
__global__ void trans_h(const float* __restrict__ in, __half* __restrict__ out,
                        int R, int C) {
    __shared__ float tile[32][33];
    int cx = blockIdx.x * 32, ry = blockIdx.y * 32;
    int tx = threadIdx.x, ty = threadIdx.y;
#pragma unroll
    for (int i = 0; i < 32; i += 8)
        tile[ty + i][tx] = in[(size_t)(ry + ty + i) * C + cx + tx];
    __syncthreads();
#pragma unroll
    for (int i = 0; i < 32; i += 8)
        out[(size_t)(cx + ty + i) * R + ry + tx] =
            __float2half_rn(tile[tx][ty + i]);
}

// elementwise fp32 -> fp16
__global__ void round_h(const float* __restrict__ in, __half* __restrict__ out,
                        int n4) {
    int i = blockIdx.x * 256 + threadIdx.x;
    if (i < n4) {
        float4 v = ((const float4*)in)[i];
        uint2 o;
        o.x = h2_u32(__floats2half2_rn(v.x, v.y));
        o.y = h2_u32(__floats2half2_rn(v.z, v.w));
        ((uint2*)out)[i] = o;
    }
}

// concat biases: out[0:3D) = q1_b|k1_b|v1_b ; out[3D:5D) = k2_b|v2_b
__global__ void bias_concat(const float* q1b, const float* k1b, const float* v1b,
                            const float* k2b, const float* v2b, float* out) {
    int i = blockIdx.x * 256 + threadIdx.x;
    if (i < DM)            out[i] = q1b[i];
    else if (i < 2 * DM)   out[i] = k1b[i - DM];
    else if (i < 3 * DM)   out[i] = v1b[i - 2 * DM];
    else if (i < 4 * DM)   out[i] = k2b[i - 3 * DM];
    else if (i < 5 * DM)   out[i] = v2b[i - 4 * DM];
}

// ---------------------------------------------------------------------------
// Block reduction for (sum, sumsq), blockDim.x == 256
// ---------------------------------------------------------------------------
__device__ __forceinline__ void block_reduce_2(float& s, float& q) {
    __shared__ float sh_s[8], sh_q[8];
    int lane = threadIdx.x & 31, w = threadIdx.x >> 5;
#pragma unroll
    for (int o = 16; o > 0; o >>= 1) {
        s += __shfl_down_sync(0xffffffffu, s, o);
        q += __shfl_down_sync(0xffffffffu, q, o);
    }
    if (lane == 0) { sh_s[w] = s; sh_q[w] = q; }
    __syncthreads();
    if (w == 0) {
        s = (lane < 8) ? sh_s[lane] : 0.f;
        q = (lane < 8) ? sh_q[lane] : 0.f;
#pragma unroll
        for (int o = 4; o > 0; o >>= 1) {
            s += __shfl_down_sync(0xffffffffu, s, o);
            q += __shfl_down_sync(0xffffffffu, q, o);
        }
        if (lane == 0) { sh_s[0] = s; sh_q[0] = q; }
    }
    __syncthreads();
    s = sh_s[0]; q = sh_q[0];
}

// ---------------------------------------------------------------------------
// Embedding gather + positional + LayerNorm; exact fp32 + fp16 outputs
// ---------------------------------------------------------------------------
__global__ void embed_ln_kernel(const int* __restrict__ tgt_ids,
                                const float* __restrict__ tok_emb,
                                const float* __restrict__ pos_emb,
                                const float* __restrict__ gam,
                                const float* __restrict__ bet,
                                float* __restrict__ out,
                                __half* __restrict__ out_r) {
    int row = blockIdx.x;
    int s   = row & (SS - 1);
    int tok = tgt_ids[row];
    const float* te = tok_emb + (size_t)tok * DM;
    const float* pe = pos_emb + (size_t)s   * DM;
    float v[4]; float sum = 0.f, sq = 0.f;
#pragma unroll
    for (int i = 0; i < 4; i++) {
        int c = threadIdx.x + i * 256;
        float x = te[c] + pe[c];
        v[i] = x; sum += x; sq += x * x;
    }
    block_reduce_2(sum, sq);
    float mu  = sum * (1.f / DM);
    float var = sq * (1.f / DM) - mu * mu;
    float rs  = rsqrtf(var + 1e-5f);
    float*  o   = out   + (size_t)row * DM;
    __half* orr = out_r + (size_t)row * DM;
#pragma unroll
    for (int i = 0; i < 4; i++) {
        int c = threadIdx.x + i * 256;
        float y = (v[i] - mu) * rs * gam[c] + bet[c];
        o[c] = y;
        orr[c] = __float2half_rn(y);
    }
}

// ---------------------------------------------------------------------------
// LayerNorm; exact fp32 + fp16 outputs
// ---------------------------------------------------------------------------
__global__ void ln_kernel(const float* __restrict__ in,
                          const float* __restrict__ gam,
                          const float* __restrict__ bet,
                          float* __restrict__ out,
                          __half* __restrict__ out_r) {
    int row = blockIdx.x;
    const float* ip = in + (size_t)row * DM;
    float v[4]; float sum = 0.f, sq = 0.f;
#pragma unroll
    for (int i = 0; i < 4; i++) {
        int c = threadIdx.x + i * 256;
        float x = ip[c];
        v[i] = x; sum += x; sq += x * x;
    }
    block_reduce_2(sum, sq);
    float mu  = sum * (1.f / DM);
    float var = sq * (1.f / DM) - mu * mu;
    float rs  = rsqrtf(var + 1e-5f);
    float*  o   = out   + (size_t)row * DM;
    __half* orr = out_r + (size_t)row * DM;
#pragma unroll
    for (int i = 0; i < 4; i++) {
        int c = threadIdx.x + i * 256;
        float y = (v[i] - mu) * rs * gam[c] + bet[c];
        o[c] = y;
        orr[c] = __float2half_rn(y);
    }
}

// ---------------------------------------------------------------------------
// FP16 mma.sync GEMM: C[M,N] = A[M,K] @ W^T (W stored [N][K] half) + bias
// (+res fp32) (gelu opt). 128x128 CTA tile, 128 threads (4 warps, 64x64),
// BK=64 (4 k-steps of m16n8k16), 3-stage cp.async pipeline.
// C written as half (out_half=1) or float.
// ---------------------------------------------------------------------------
#define BKH    64
#define PADH   72                              // halfs per smem row
#define TILE_H (128 * PADH)                    // halfs per operand
#define STAGE_H (2 * TILE_H)                   // halfs per stage
#define GEMM_SMEM_BYTES (3 * STAGE_H * 2)      // 110592 B

__global__ __launch_bounds__(128) void gemm_h(
    const __half* __restrict__ A, const __half* __restrict__ W,
    const float* __restrict__ bias, const float* __restrict__ res,
    void* __restrict__ Cout, int M, int N, int K, int gelu, int out_half) {
    extern __shared__ __half smh[];
    uint32_t sbase = smem_u32(smh);

    int tid  = threadIdx.x;
    int wid  = tid >> 5, lane = tid & 31;
    int gid  = lane >> 2, tig = lane & 3;
    int m_off = (wid >> 1) * 64;
    int n_off = (wid & 1) * 64;
    int bm = blockIdx.y * 128, bn = blockIdx.x * 128;

    float acc[4][8][4];
#pragma unroll
    for (int i = 0; i < 4; i++)
#pragma unroll
        for (int j = 0; j < 8; j++)
#pragma unroll
            for (int k = 0; k < 4; k++) acc[i][j][k] = 0.f;

    const int T = K / BKH;

    auto issue = [&](int s, int kt) {
        uint32_t aU = sbase + (uint32_t)(s * STAGE_H) * 2;
        uint32_t bU = aU + (uint32_t)TILE_H * 2;
        int k0 = kt * BKH;
#pragma unroll
        for (int i = 0; i < 8; i++) {
            int idx = tid + i * 128;
            int r = idx >> 3, c8 = (idx & 7) * 8;
            cp16(aU + (uint32_t)(r * PADH + c8) * 2,
                 A + (size_t)(bm + r) * K + k0 + c8);
        }
#pragma unroll
        for (int i = 0; i < 8; i++) {
            int idx = tid + i * 128;
            int r = idx >> 3, c8 = (idx & 7) * 8;
            cp16(bU + (uint32_t)(r * PADH + c8) * 2,
                 W + (size_t)(bn + r) * K + k0 + c8);
        }
        CP_COMMIT();
    };

    issue(0, 0);
    issue(1, 1);

    for (int t = 0; t < T; t++) {
        int cur = t % 3;
        CP_WAIT(1);
        __syncthreads();
        if (t + 2 < T) issue((t + 2) % 3, t + 2);

        const __half* Ah = smh + cur * STAGE_H;
        const __half* Bh = Ah + TILE_H;
#pragma unroll
        for (int ks = 0; ks < 4; ks++) {
            int k = ks * 16;
            uint32_t a[4][4], b[8][2];
#pragma unroll
            for (int mf = 0; mf < 4; mf++) {
                const __half* p = Ah + (m_off + mf * 16 + gid) * PADH + k + 2 * tig;
                a[mf][0] = *(const uint32_t*)(p);
                a[mf][1] = *(const uint32_t*)(p + 8 * PADH);
                a[mf][2] = *(const uint32_t*)(p + 8);
                a[mf][3] = *(const uint32_t*)(p + 8 * PADH + 8);
            }
#pragma unroll
            for (int nf = 0; nf < 8; nf++) {
                const __half* p = Bh + (n_off + nf * 8 + gid) * PADH + k + 2 * tig;
                b[nf][0] = *(const uint32_t*)(p);
                b[nf][1] = *(const uint32_t*)(p + 8);
            }
#pragma unroll
            for (int mf = 0; mf < 4; mf++)
#pragma unroll
                for (int nf = 0; nf < 8; nf++)
                    mma_f16(acc[mf][nf], a[mf], b[nf]);
        }
    }

#pragma unroll
    for (int mf = 0; mf < 4; mf++) {
        int row0 = bm + m_off + mf * 16 + gid;
        int row1 = row0 + 8;
#pragma unroll
        for (int nf = 0; nf < 8; nf++) {
            int col = bn + n_off + nf * 8 + 2 * tig;
            float b0 = bias[col], b1 = bias[col + 1];
            float v0 = acc[mf][nf][0] + b0;
            float v1 = acc[mf][nf][1] + b1;
            float v2 = acc[mf][nf][2] + b0;
            float v3 = acc[mf][nf][3] + b1;
            if (res) {
                v0 += res[(size_t)row0 * N + col];
                v1 += res[(size_t)row0 * N + col + 1];
                v2 += res[(size_t)row1 * N + col];
                v3 += res[(size_t)row1 * N + col + 1];
            }
            if (gelu) {
                v0 = 0.5f * v0 * (1.0f + erff(v0 * 0.70710678118654752f));
                v1 = 0.5f * v1 * (1.0f + erff(v1 * 0.70710678118654752f));
                v2 = 0.5f * v2 * (1.0f + erff(v2 * 0.70710678118654752f));
                v3 = 0.5f * v3 * (1.0f + erff(v3 * 0.70710678118654752f));
            }
            if (out_half) {
                __half* C = (__half*)Cout;
                *(__half2*)(C + (size_t)row0 * N + col) = __floats2half2_rn(v0, v1);
                *(__half2*)(C + (size_t)row1 * N + col) = __floats2half2_rn(v2, v3);
            } else {
                float* C = (float*)Cout;
                *(float2*)(C + (size_t)row0 * N + col) = make_float2(v0, v1);
                *(float2*)(C + (size_t)row1 * N + col) = make_float2(v2, v3);
            }
        }
    }
}

// ---------------------------------------------------------------------------
// FP16 tensor-core flash attention with register-prefetch pipeline.
// Q/K/V half (packed strides), O half. 128 threads, 64 q-rows/block.
// ---------------------------------------------------------------------------
#define AP 72
#define ATTN_SMEM_BYTES (3 * 64 * AP * 2 + 64 * 4)

__global__ __launch_bounds__(128) void attn_h(
    const __half* __restrict__ Q, const __half* __restrict__ Kb,
    const __half* __restrict__ Vb, const int* __restrict__ ids,
    __half* __restrict__ O, int causal, int stq, int stkv) {
    extern __shared__ __half smh[];
    __half* Ks = smh;                  // [64][AP]  keys x dh
    __half* Vt = smh + 64 * AP;        // [64][AP]  dh x keys
    __half* Ps = smh + 2 * 64 * AP;    // [64][AP]  q x keys
    float*  pm = (float*)(smh + 3 * 64 * AP);

    int b   = blockIdx.y >> 4;
    int h   = blockIdx.y & 15;
    int q0  = blockIdx.x * 64;
    int tid = threadIdx.x;
    int wid = tid >> 5, lane = tid & 31;
    int gid = lane >> 2, tig = lane & 3;
    int lrow = wid * 16 + gid;
    int grow = q0 + lrow;

    // Q fragments (A operand), 4 k-steps of 16 dh
    uint32_t qf[4][4];
    const __half* qb0 = Q + ((size_t)(b * SS + grow)) * stq + h * DHD;
    const __half* qb8 = qb0 + (size_t)8 * stq;
#pragma unroll
    for (int ks = 0; ks < 4; ks++) {
        int k = ks * 16 + 2 * tig;
        qf[ks][0] = *(const uint32_t*)(qb0 + k);
        qf[ks][1] = *(const uint32_t*)(qb8 + k);
        qf[ks][2] = *(const uint32_t*)(qb0 + k + 8);
        qf[ks][3] = *(const uint32_t*)(qb8 + k + 8);
    }

    float of[8][4];
#pragma unroll
    for (int i = 0; i < 8; i++)
#pragma unroll
        for (int j = 0; j < 4; j++) of[i][j] = 0.f;
    float m0 = -1e30f, m1 = -1e30f, l0 = 0.f, l1 = 0.f;

    int ntiles = causal ? (blockIdx.x + 1) : (SS / 64);

    // register prefetch state
    uint4 kvr[4], vvr[4];
    int idv = 0;
    auto loadtile = [&](int t) {
        int kbase = t * 64;
#pragma unroll
        for (int i = 0; i < 4; i++) {
            int e  = tid + i * 128;
            int r  = e >> 3, c8 = (e & 7) * 8;
            size_t goff = ((size_t)(b * SS + kbase + r)) * stkv + h * DHD + c8;
            kvr[i] = *(const uint4*)(Kb + goff);
            vvr[i] = *(const uint4*)(Vb + goff);
        }
        if (tid < 64) idv = ids[b * SS + kbase + tid];
    };

    loadtile(0);
    for (int t = 0; t < ntiles; t++) {
        int kbase = t * 64;
        // store phase (from registers)
#pragma unroll
        for (int i = 0; i < 4; i++) {
            int e  = tid + i * 128;
            int r  = e >> 3, c8 = (e & 7) * 8;
            *(uint4*)(Ks + r * AP + c8) = kvr[i];
            const __half* vh = (const __half*)&vvr[i];
#pragma unroll
            for (int j = 0; j < 8; j++)
                Vt[(c8 + j) * AP + r] = vh[j];
        }
        if (tid < 64)
            pm[tid] = (idv == 0) ? NEGBIG : 0.f;
        __syncthreads();
        if (t + 1 < ntiles) loadtile(t + 1);

        // S = Q @ K^T
        float sf[8][4];
#pragma unroll
        for (int nf = 0; nf < 8; nf++) {
            sf[nf][0] = 0.f; sf[nf][1] = 0.f; sf[nf][2] = 0.f; sf[nf][3] = 0.f;
#pragma unroll
            for (int ks = 0; ks < 4; ks++) {
                uint32_t bf[2];
                const __half* p = Ks + (nf * 8 + gid) * AP + ks * 16 + 2 * tig;
                bf[0] = *(const uint32_t*)(p);
                bf[1] = *(const uint32_t*)(p + 8);
                mma_f16(sf[nf], qf[ks], bf);
            }
        }

        float tmax0 = -1e30f, tmax1 = -1e30f;
#pragma unroll
        for (int nf = 0; nf < 8; nf++) {
            int lc0 = nf * 8 + 2 * tig, lc1 = lc0 + 1;
            float s0 = sf[nf][0] * 0.125f + pm[lc0];
            float s1 = sf[nf][1] * 0.125f + pm[lc1];
            float s2 = sf[nf][2] * 0.125f + pm[lc0];
            float s3 = sf[nf][3] * 0.125f + pm[lc1];
            if (causal) {
                int g0 = kbase + lc0, g1 = kbase + lc1;
                if (g0 > grow)     s0 = -1e30f;
                if (g1 > grow)     s1 = -1e30f;
                if (g0 > grow + 8) s2 = -1e30f;
                if (g1 > grow + 8) s3 = -1e30f;
            }
            sf[nf][0] = s0; sf[nf][1] = s1; sf[nf][2] = s2; sf[nf][3] = s3;
            tmax0 = fmaxf(tmax0, fmaxf(s0, s1));
            tmax1 = fmaxf(tmax1, fmaxf(s2, s3));
        }
        tmax0 = fmaxf(tmax0, __shfl_xor_sync(0xffffffffu, tmax0, 1));
        tmax0 = fmaxf(tmax0, __shfl_xor_sync(0xffffffffu, tmax0, 2));
        tmax1 = fmaxf(tmax1, __shfl_xor_sync(0xffffffffu, tmax1, 1));
        tmax1 = fmaxf(tmax1, __shfl_xor_sync(0xffffffffu, tmax1, 2));

        float nm0 = fmaxf(m0, tmax0), nm1 = fmaxf(m1, tmax1);
        float sc0 = __expf(m0 - nm0), sc1 = __expf(m1 - nm1);
        m0 = nm0; m1 = nm1;

        float ts0 = 0.f, ts1 = 0.f;
        __half* pr0 = Ps + lrow * AP;
        __half* pr1 = Ps + (lrow + 8) * AP;
#pragma unroll
        for (int nf = 0; nf < 8; nf++) {
            int lc0 = nf * 8 + 2 * tig;
            float p0 = __expf(sf[nf][0] - nm0);
            float p1 = __expf(sf[nf][1] - nm0);
            float p2 = __expf(sf[nf][2] - nm1);
            float p3 = __expf(sf[nf][3] - nm1);
            ts0 += p0 + p1; ts1 += p2 + p3;
            *(__half2*)(pr0 + lc0) = __floats2half2_rn(p0, p1);
            *(__half2*)(pr1 + lc0) = __floats2half2_rn(p2, p3);
            of[nf][0] *= sc0; of[nf][1] *= sc0;
            of[nf][2] *= sc1; of[nf][3] *= sc1;
        }
        ts0 += __shfl_xor_sync(0xffffffffu, ts0, 1);
        ts0 += __shfl_xor_sync(0xffffffffu, ts0, 2);
        ts1 += __shfl_xor_sync(0xffffffffu, ts1, 1);
        ts1 += __shfl_xor_sync(0xffffffffu, ts1, 2);
        l0 = l0 * sc0 + ts0;
        l1 = l1 * sc1 + ts1;
        __syncwarp();

        // O += P @ V
#pragma unroll
        for (int ks = 0; ks < 4; ks++) {
            int kk = ks * 16 + 2 * tig;
            uint32_t af[4];
            af[0] = *(const uint32_t*)(pr0 + kk);
            af[1] = *(const uint32_t*)(pr1 + kk);
            af[2] = *(const uint32_t*)(pr0 + kk + 8);
            af[3] = *(const uint32_t*)(pr1 + kk + 8);
#pragma unroll
            for (int nf = 0; nf < 8; nf++) {
                uint32_t bf[2];
                const __half* p = Vt + (nf * 8 + gid) * AP + ks * 16 + 2 * tig;
                bf[0] = *(const uint32_t*)(p);
                bf[1] = *(const uint32_t*)(p + 8);
                mma_f16(of[nf], af, bf);
            }
        }
        __syncthreads();
    }

    float inv0 = 1.f / l0, inv1 = 1.f / l1;
    __half* ob0 = O + ((size_t)(b * SS + grow)) * DM + h * DHD;
    __half* ob8 = ob0 + (size_t)8 * DM;
#pragma unroll
    for (int nf = 0; nf < 8; nf++) {
        int col = nf * 8 + 2 * tig;
        *(__half2*)(ob0 + col) = __floats2half2_rn(of[nf][0] * inv0, of[nf][1] * inv0);
        *(__half2*)(ob8 + col) = __floats2half2_rn(of[nf][2] * inv1, of[nf][3] * inv1);
    }
}

// ---------------------------------------------------------------------------
// Launch
// ---------------------------------------------------------------------------
extern "C" void kernel_launch(void* const* d_in, const int* in_sizes, int n_in,
                              void* d_out, int out_size) {
    const float* input_embedding = (const float*)d_in[0];
    const int*   input_ids       = (const int*)d_in[1];
    const int*   target_ids      = (const int*)d_in[2];
    const float* tok_emb = (const float*)d_in[3];
    const float* pos_emb = (const float*)d_in[4];
    const float* ln1_g = (const float*)d_in[5];
    const float* ln1_b = (const float*)d_in[6];
    const float* q1_w = (const float*)d_in[7];
    const float* q1_b = (const float*)d_in[8];
    const float* k1_w = (const float*)d_in[9];
    const float* k1_b = (const float*)d_in[10];
    const float* v1_w = (const float*)d_in[11];
    const float* v1_b = (const float*)d_in[12];
    const float* out1_w = (const float*)d_in[13];
    const float* out1_b = (const float*)d_in[14];
    const float* ln2_g = (const float*)d_in[15];
    const float* ln2_b = (const float*)d_in[16];
    const float* q2_w = (const float*)d_in[17];
    const float* q2_b = (const float*)d_in[18];
    const float* k2_w = (const float*)d_in[19];
    const float* k2_b = (const float*)d_in[20];
    const float* v2_w = (const float*)d_in[21];
    const float* v2_b = (const float*)d_in[22];
    const float* out2_w = (const float*)d_in[23];
    const float* out2_b = (const float*)d_in[24];
    const float* ln3_g = (const float*)d_in[25];
    const float* ln3_b = (const float*)d_in[26];
    const float* mlp_w1 = (const float*)d_in[27];
    const float* mlp_b1 = (const float*)d_in[28];
    const float* mlp_w2 = (const float*)d_in[29];
    const float* mlp_b2 = (const float*)d_in[30];
    float* out = (float*)d_out;

    static float  *X = nullptr, *H = nullptr, *BI = nullptr;
    static __half *XR = nullptr, *ER = nullptr, *QKV = nullptr, *KV = nullptr,
                  *Qh = nullptr, *ATT = nullptr, *HID = nullptr, *WTh = nullptr;
    static bool attr_done = false;
    if (!X) {
        cudaGetSymbolAddress((void**)&X,   g_X);
        cudaGetSymbolAddress((void**)&XR,  g_XR);
        cudaGetSymbolAddress((void**)&ER,  g_ER);
        cudaGetSymbolAddress((void**)&QKV, g_QKV);
        cudaGetSymbolAddress((void**)&KV,  g_KV);
        cudaGetSymbolAddress((void**)&Qh,  g_Q);
        cudaGetSymbolAddress((void**)&ATT, g_ATT);
        cudaGetSymbolAddress((void**)&H,   g_H);
        cudaGetSymbolAddress((void**)&HID, g_HID);
        cudaGetSymbolAddress((void**)&WTh, g_WTh);
        cudaGetSymbolAddress((void**)&BI,  g_BI);
    }
    if (!attr_done) {
        cudaFuncSetAttribute(gemm_h, cudaFuncAttributeMaxDynamicSharedMemorySize,
                             GEMM_SMEM_BYTES);
        cudaFuncSetAttribute(attn_h, cudaFuncAttributeMaxDynamicSharedMemorySize,
                             ATTN_SMEM_BYTES);
        attr_done = true;
    }

    const size_t MH = 1024 * 1024;
    __half* wr_qkv = WTh + 0 * MH;    // [3072][1024]
    __half* wr_kv2 = WTh + 3 * MH;    // [2048][1024]
    __half* wr_q2  = WTh + 5 * MH;    // [1024][1024]
    __half* wr_o1  = WTh + 6 * MH;
    __half* wr_o2  = WTh + 7 * MH;
    __half* wr_m1  = WTh + 8 * MH;    // [4096][1024]
    __half* wr_m2  = WTh + 12 * MH;   // [1024][4096]
    float* bqkv = BI;
    float* bkv2 = BI + 3 * DM;

    // batched DM x DM weight transposes (8 in one launch)
    TransBatch tbat;
    tbat.src[0] = q1_w;   tbat.dst[0] = wr_qkv;
    tbat.src[1] = k1_w;   tbat.dst[1] = wr_qkv + (size_t)DM * DM;
    tbat.src[2] = v1_w;   tbat.dst[2] = wr_qkv + (size_t)2 * DM * DM;
    tbat.src[3] = k2_w;   tbat.dst[3] = wr_kv2;
    tbat.src[4] = v2_w;   tbat.dst[4] = wr_kv2 + (size_t)DM * DM;
    tbat.src[5] = q2_w;   tbat.dst[5] = wr_q2;
    tbat.src[6] = out1_w; tbat.dst[6] = wr_o1;
    tbat.src[7] = out2_w; tbat.dst[7] = wr_o2;
    dim3 tb(32, 8);
    dim3 tg8(DM / 32, DM / 32, 8);
    trans_h8<<<tg8, tb>>>(tbat);
    dim3 tgm1(DFF / 32, DM / 32);            // mlp_w1 [1024][4096]
    trans_h<<<tgm1, tb>>>(mlp_w1, wr_m1, DM, DFF);
    dim3 tgm2(DM / 32, DFF / 32);            // mlp_w2 [4096][1024]
    trans_h<<<tgm2, tb>>>(mlp_w2, wr_m2, DFF, DM);
    round_h<<<(MTOK * DM / 4) / 256, 256>>>(input_embedding, ER, MTOK * DM / 4);
    bias_concat<<<20, 256>>>(q1_b, k1_b, v1_b, k2_b, v2_b, BI);

    dim3 gQKV(3 * DM / 128, MTOK / 128);   // (24, 32)
    dim3 gKV (2 * DM / 128, MTOK / 128);   // (16, 32)
    dim3 gProj(DM / 128, MTOK / 128);      // (8, 32)
    dim3 gMlp1(DFF / 128, MTOK / 128);     // (32, 32)
    dim3 gAttn(SS / 64, BB * HH);          // (32, 32)
    const int SB = GEMM_SMEM_BYTES;
    const int AB = ATTN_SMEM_BYTES;

    // 1. embedding + LN1 -> X (fp32), XR (fp16)
    embed_ln_kernel<<<MTOK, 256>>>(target_ids, tok_emb, pos_emb, ln1_g, ln1_b, X, XR);
    // 2. fused QKV projection -> QKV (fp16)
    gemm_h<<<gQKV, 128, SB>>>(XR, wr_qkv, bqkv, nullptr, QKV, MTOK, 3 * DM, DM, 0, 1);
    // 3. causal self-attention (packed QKV, stride 3*DM) -> ATT (fp16)
    attn_h<<<gAttn, 128, AB>>>(QKV, QKV + DM, QKV + 2 * DM, target_ids, ATT, 1,
                               3 * DM, 3 * DM);
    // 4. out projection + residual (X) -> H (fp32)
    gemm_h<<<gProj, 128, SB>>>(ATT, wr_o1, out1_b, X, H, MTOK, DM, DM, 0, 0);
    // 5. LN2 -> X, XR
    ln_kernel<<<MTOK, 256>>>(H, ln2_g, ln2_b, X, XR);
    // 6. cross-attn projections: Q2 (from XR), fused KV2 (from ER)
    gemm_h<<<gProj, 128, SB>>>(XR, wr_q2, q2_b, nullptr, Qh, MTOK, DM, DM, 0, 1);
    gemm_h<<<gKV, 128, SB>>>(ER, wr_kv2, bkv2, nullptr, KV, MTOK, 2 * DM, DM, 0, 1);
    // 7. cross-attention (Q stride DM, KV stride 2*DM) -> ATT (fp16)
    attn_h<<<gAttn, 128, AB>>>(Qh, KV, KV + DM, input_ids, ATT, 0, DM, 2 * DM);
    // 8. out projection + residual (X = LN2 out) -> H (fp32, "r")
    gemm_h<<<gProj, 128, SB>>>(ATT, wr_o2, out2_b, X, H, MTOK, DM, DM, 0, 0);
    // 9. LN3 -> X, XR
    ln_kernel<<<MTOK, 256>>>(H, ln3_g, ln3_b, X, XR);
    // 10. MLP up + GELU -> HID (fp16)
    gemm_h<<<gMlp1, 128, SB>>>(XR, wr_m1, mlp_b1, nullptr, HID, MTOK, DFF, DM, 1, 1);
    // 11. MLP down + bias + residual (H) -> out (fp32)
    gemm_h<<<gProj, 128, SB>>>(HID, wr_m2, mlp_b2, H, out, MTOK, DM, DFF, 0, 0);
}